// round 1
// baseline (speedup 1.0000x reference)
#include <cuda_runtime.h>

// CapsNet dynamic routing, factorized form. One CTA handles BT=2 batches.
// Never materializes u (B,O,N,E): uses
//   y[o,uq,f]  = sum_s c[o,n] x[n,f]
//   s[o,e]     = sum_{uq,f} W[o,uq,e,f] y[o,uq,f]      (v = squash(s))
//   wv[o,uq,f] = sum_e W[o,uq,e,f] v[o,e]
//   b[o,n]    += sum_f x[n,f] wv[o,uq,f]
// Softmax state kept as eb = exp(b) (multiplicative update), rd = 1/sum_o eb.

namespace {
constexpr int O_ = 10, U_ = 36, S_ = 32, E_ = 16, F_ = 8;
constexpr int N_ = U_ * S_;          // 1152
constexpr int B_ = 256;
constexpr int BT = 2;
constexpr int ITERS_ = 3;
constexpr int T_ = 512;
constexpr int NP = N_ + 4;           // padded eb row (break 128B-stride conflicts)

// shared layout (floats)
constexpr int OFF_XS  = 0;                         // [BT][N][F]     18432
constexpr int OFF_EB  = OFF_XS + BT * N_ * F_;     // [BT][O][NP]    23120
constexpr int OFF_RD  = OFF_EB + BT * O_ * NP;     // [BT][N]         2304
constexpr int OFF_Y   = OFF_RD + BT * N_;          // [BT][O][U][F]   5760
constexpr int OFF_SVP = OFF_Y + BT * O_ * U_ * F_; // [BT][O][E][4]   1280
constexpr int OFF_VV  = OFF_SVP + BT * O_ * E_ * 4;// [BT][O][E]       320
constexpr int SM_FLOATS = OFF_VV + BT * O_ * E_;   // 51216 -> 204864 B
} // namespace

__global__ __launch_bounds__(T_, 1)
void caps_route_kernel(const float* __restrict__ x,
                       const float* __restrict__ Wg,
                       float* __restrict__ out) {
    extern __shared__ float sm[];
    float* xs = sm + OFF_XS;
    float* eb = sm + OFF_EB;
    float* rd = sm + OFF_RD;
    float* yb = sm + OFF_Y;     // also reused as wv
    float* svp = sm + OFF_SVP;
    float* vv = sm + OFF_VV;

    const int tid = threadIdx.x;
    const int b0 = blockIdx.x * BT;

    const float4* __restrict__ wp4 = reinterpret_cast<const float4*>(Wg);
    float4* xs4 = reinterpret_cast<float4*>(xs);
    float4* yb4 = reinterpret_cast<float4*>(yb);

    // ---- load x tiles (coalesced float4), init routing state ----
    {
        const float4* xg = reinterpret_cast<const float4*>(x) + (size_t)b0 * (N_ * F_ / 4);
        #pragma unroll 4
        for (int i = tid; i < BT * N_ * F_ / 4; i += T_) xs4[i] = xg[i];
    }
    for (int i = tid; i < BT * O_ * NP; i += T_) eb[i] = 1.0f;   // exp(0)
    for (int i = tid; i < BT * N_; i += T_) rd[i] = 0.1f;        // 1/O
    __syncthreads();

    for (int it = 0; it <= ITERS_; ++it) {
        // ---- phase 2: y[bb][o][u][fg(f4)] ; 20 roles per (bb,u) task ----
        for (int i = tid; i < BT * U_ * 20; i += T_) {
            const int role = i % 20;
            const int tsk = i / 20;         // (bb,u)
            const int bb = tsk / U_;
            const int u = tsk % U_;
            const int o = role >> 1;
            const int fg = role & 1;
            const float* ebp = eb + (bb * O_ + o) * NP + u * S_;
            const float* rdp = rd + bb * N_ + u * S_;
            const float4* xp = xs4 + ((bb * N_ + u * S_) * 2 + fg);
            float4 acc = make_float4(0.f, 0.f, 0.f, 0.f);
            #pragma unroll 8
            for (int s = 0; s < S_; ++s) {
                float c = ebp[s] * rdp[s];
                float4 xv = xp[s * 2];
                acc.x += c * xv.x; acc.y += c * xv.y;
                acc.z += c * xv.z; acc.w += c * xv.w;
            }
            yb4[((bb * O_ + o) * U_ + u) * 2 + fg] = acc;
        }
        __syncthreads();

        // ---- phase 3: partial s-vec over u-chunks; W read once serves both bb ----
        for (int i = tid; i < O_ * E_ * 4; i += T_) {
            const int o = i >> 6;
            const int e = (i >> 2) & 15;
            const int uc = i & 3;
            float p0 = 0.f, p1 = 0.f;
            #pragma unroll
            for (int j = 0; j < 9; ++j) {
                const int u = uc * 9 + j;
                const int wbase = ((o * U_ + u) * E_ + e) * 2;
                float4 w0 = wp4[wbase + 0];
                float4 w1 = wp4[wbase + 1];
                const int ia = (o * U_ + u) * 2;            // bb=0
                const int ib = ((O_ + o) * U_ + u) * 2;     // bb=1
                float4 a0 = yb4[ia + 0], a1 = yb4[ia + 1];
                float4 c0 = yb4[ib + 0], c1 = yb4[ib + 1];
                p0 += w0.x * a0.x + w0.y * a0.y + w0.z * a0.z + w0.w * a0.w;
                p0 += w1.x * a1.x + w1.y * a1.y + w1.z * a1.z + w1.w * a1.w;
                p1 += w0.x * c0.x + w0.y * c0.y + w0.z * c0.z + w0.w * c0.w;
                p1 += w1.x * c1.x + w1.y * c1.y + w1.z * c1.z + w1.w * c1.w;
            }
            svp[((o * E_ + e)) * 4 + uc] = p0;
            svp[((O_ * E_ + o * E_ + e)) * 4 + uc] = p1;
        }
        __syncthreads();

        // ---- phase 4: reduce partials + squash -> vv (20 threads) ----
        if (tid < BT * O_) {
            const int bb = tid / O_, o = tid % O_;
            float sv[E_];
            float nsq = 0.f;
            #pragma unroll
            for (int e = 0; e < E_; ++e) {
                const float* p = svp + ((bb * O_ + o) * E_ + e) * 4;
                float s = (p[0] + p[1]) + (p[2] + p[3]);
                sv[e] = s;
                nsq += s * s;
            }
            const float nrm = sqrtf(nsq);
            const float sc = nrm / (1.f + nsq);
            #pragma unroll
            for (int e = 0; e < E_; ++e) vv[(bb * O_ + o) * E_ + e] = sv[e] * sc;
        }
        __syncthreads();

        if (it == ITERS_) break;

        // ---- phase 5: wv[bb][o][u][fg] into yb; W read once serves both bb ----
        for (int i = tid; i < O_ * U_ * 2; i += T_) {
            const int fg = i & 1;
            const int ou = i >> 1;
            const int o = ou / U_, u = ou % U_;
            const float4* wp = wp4 + ((o * U_ + u) * E_ * 2 + fg);
            const float* v0 = vv + o * E_;
            const float* v1 = vv + (O_ + o) * E_;
            float4 a0 = make_float4(0.f, 0.f, 0.f, 0.f);
            float4 a1 = make_float4(0.f, 0.f, 0.f, 0.f);
            #pragma unroll
            for (int e = 0; e < E_; ++e) {
                float4 w = wp[e * 2];
                float ve0 = v0[e], ve1 = v1[e];
                a0.x += ve0 * w.x; a0.y += ve0 * w.y;
                a0.z += ve0 * w.z; a0.w += ve0 * w.w;
                a1.x += ve1 * w.x; a1.y += ve1 * w.y;
                a1.z += ve1 * w.z; a1.w += ve1 * w.w;
            }
            yb4[((0 * O_ + o) * U_ + u) * 2 + fg] = a0;
            yb4[((1 * O_ + o) * U_ + u) * 2 + fg] = a1;
        }
        __syncthreads();

        // ---- phase 6: eb[o][n] *= exp(dot(x[n], wv[o,u])); rd[n] = 1/sum_o eb ----
        for (int i = tid; i < BT * N_; i += T_) {
            const int bb = i / N_, n = i % N_;
            const int u = n >> 5;
            const float4* xp = xs4 + (bb * N_ + n) * 2;
            const float4 x0 = xp[0], x1 = xp[1];
            float* ebp = eb + bb * O_ * NP + n;
            const float4* wvb = yb4 + (bb * O_ * U_ + u) * 2;
            float ssum = 0.f;
            #pragma unroll
            for (int o = 0; o < O_; ++o) {
                float4 w0 = wvb[o * U_ * 2], w1 = wvb[o * U_ * 2 + 1];
                float d = x0.x * w0.x + x0.y * w0.y + x0.z * w0.z + x0.w * w0.w
                        + x1.x * w1.x + x1.y * w1.y + x1.z * w1.z + x1.w * w1.w;
                float nv = ebp[o * NP] * __expf(d);
                ebp[o * NP] = nv;
                ssum += nv;
            }
            rd[i] = 1.0f / ssum;
        }
        __syncthreads();
    }

    // ---- write out[b][o][e] ----
    if (tid < BT * O_ * E_) {
        const int bb = tid / (O_ * E_);
        out[(size_t)(b0 + bb) * (O_ * E_) + (tid - bb * O_ * E_)] = vv[tid];
    }
}

extern "C" void kernel_launch(void* const* d_in, const int* in_sizes, int n_in,
                              void* d_out, int out_size) {
    (void)in_sizes; (void)n_in; (void)out_size;
    const float* x = (const float*)d_in[0];
    const float* W = (const float*)d_in[1];
    float* out = (float*)d_out;

    const size_t smem = (size_t)SM_FLOATS * sizeof(float);  // 204,864 B
    cudaFuncSetAttribute(caps_route_kernel,
                         cudaFuncAttributeMaxDynamicSharedMemorySize, (int)smem);
    caps_route_kernel<<<B_ / BT, T_, smem>>>(x, W, out);
}

// round 2
// speedup vs baseline: 1.0265x; 1.0265x over previous
#include <cuda_runtime.h>

// CapsNet dynamic routing, factorized (u never materialized):
//   y[o,u,f]  = sum_s c[o,n] x[n,f]
//   s[o,e]    = sum_{u,f} W[o,u,e,f] y[o,u,f]   ; v = squash(s)
//   wv[o,u,f] = sum_e W[o,u,e,f] v[o,e]
//   c[o,n]   <- normalize_o( c[o,n] * exp(sum_f x[n,f] wv[o,u,f]) )
// c stored renormalized each iteration (softmax shift-invariance) -> no rd array.

namespace {
constexpr int O_ = 10, U_ = 36, E_ = 16, F_ = 8;
constexpr int N_ = U_ * 32;          // 1152
constexpr int B_ = 256;
constexpr int BT = 2;
constexpr int ITERS_ = 3;
constexpr int T_ = 576;              // 18 warps
constexpr int NP = 1157;             // padded c row stride (odd-ish vs 32 banks)

// shared layout (floats)
constexpr int OFF_XS  = 0;                          // [BT][N][F]          18432
constexpr int OFF_C   = OFF_XS + BT * N_ * F_;      // [BT][O][NP]         23140
constexpr int OFF_P   = OFF_C + BT * O_ * NP;       // partial [576][20]   11520
constexpr int OFF_SVP = OFF_P + T_ * 20;            // [BT][O][E][4]        1280
constexpr int OFF_VV  = OFF_SVP + BT * O_ * E_ * 4; // [BT][O][E]            320
constexpr int SM_FLOATS = OFF_VV + BT * O_ * E_;    // 54692 -> 218768 B
constexpr int WVO = 5760;  // wv region inside partial buffer (rows 288..575)
} // namespace

__global__ __launch_bounds__(T_, 1)
void caps_route_kernel(const float* __restrict__ x,
                       const float* __restrict__ Wg,
                       float* __restrict__ out) {
    extern __shared__ float sm[];
    float* xs  = sm + OFF_XS;
    float* cc  = sm + OFF_C;
    float* pb  = sm + OFF_P;
    float* svp = sm + OFF_SVP;
    float* vv  = sm + OFF_VV;

    const int tid = threadIdx.x;
    const int b0 = blockIdx.x * BT;

    const float4* __restrict__ wp4 = reinterpret_cast<const float4*>(Wg);
    float4* xs4 = reinterpret_cast<float4*>(xs);

    // ---- load x tiles (coalesced float4), init c = 1/O ----
    {
        const float4* xg = reinterpret_cast<const float4*>(x) + (size_t)b0 * (N_ * F_ / 4);
        #pragma unroll 4
        for (int i = tid; i < BT * N_ * F_ / 4; i += T_) xs4[i] = xg[i];
    }
    for (int i = tid; i < BT * O_ * NP; i += T_) cc[i] = 0.1f;
    __syncthreads();

    // ---- phase-2 task decode: tid = sh*288 + oh*144 + fg*72 + bb*36 + u ----
    const int sh  = (tid >= 288);
    const int r1  = tid - sh * 288;
    const int oh  = (r1 >= 144);
    const int r2  = r1 - oh * 144;
    const int fg  = (r2 >= 72);
    const int q   = r2 - fg * 72;
    const int bb2 = (q >= 36);
    const int u2  = q - bb2 * 36;
    float* cbase = cc + (bb2 * O_ + oh * 5) * NP + u2 * 32 + sh * 16;
    const float4* xbase = xs4 + (bb2 * N_ + u2 * 32 + sh * 16) * 2 + fg;
    float4* prow = reinterpret_cast<float4*>(pb + tid * 20);

    for (int it = 0; it <= ITERS_; ++it) {
        // ---- phase 2: partial y for (bb,u,fg,oh,sh); 5 o-accumulators ----
        {
            float4 a0 = make_float4(0.f,0.f,0.f,0.f), a1 = a0, a2 = a0, a3 = a0, a4 = a0;
            #pragma unroll
            for (int j = 0; j < 16; ++j) {
                const int s = (u2 + j) & 15;             // rotation: bank decollide
                const float4 xv = xbase[s * 2];
                const float c0 = cbase[0 * NP + s];
                const float c1 = cbase[1 * NP + s];
                const float c2 = cbase[2 * NP + s];
                const float c3 = cbase[3 * NP + s];
                const float c4 = cbase[4 * NP + s];
                a0.x += c0 * xv.x; a0.y += c0 * xv.y; a0.z += c0 * xv.z; a0.w += c0 * xv.w;
                a1.x += c1 * xv.x; a1.y += c1 * xv.y; a1.z += c1 * xv.z; a1.w += c1 * xv.w;
                a2.x += c2 * xv.x; a2.y += c2 * xv.y; a2.z += c2 * xv.z; a2.w += c2 * xv.w;
                a3.x += c3 * xv.x; a3.y += c3 * xv.y; a3.z += c3 * xv.z; a3.w += c3 * xv.w;
                a4.x += c4 * xv.x; a4.y += c4 * xv.y; a4.z += c4 * xv.z; a4.w += c4 * xv.w;
            }
            prow[0] = a0; prow[1] = a1; prow[2] = a2; prow[3] = a3; prow[4] = a4;
        }
        __syncthreads();

        // ---- reduce the two s-halves in place (rows [0,288) += rows [288,576)) ----
        if (tid < 288) {
            float4* d = reinterpret_cast<float4*>(pb + tid * 20);
            const float4* s2 = reinterpret_cast<const float4*>(pb + (tid + 288) * 20);
            #pragma unroll
            for (int k = 0; k < 5; ++k) {
                float4 a = d[k], b = s2[k];
                a.x += b.x; a.y += b.y; a.z += b.z; a.w += b.w;
                d[k] = a;
            }
        }
        __syncthreads();

        // ---- phase 3: s[bb,o,e] partials over u-chunks; W from global once ----
        for (int i = tid; i < O_ * E_ * 4; i += T_) {
            const int o = i >> 6;
            const int e = (i >> 2) & 15;
            const int uc = i & 3;
            const int ohh = o / 5, ol = o - ohh * 5;
            float p0 = 0.f, p1 = 0.f;
            #pragma unroll
            for (int jj = 0; jj < 9; ++jj) {
                const int u = uc * 9 + jj;
                const int wb = ((o * U_ + u) * E_ + e) * 2;
                const float4 w0 = wp4[wb + 0];
                const float4 w1 = wp4[wb + 1];
                const int rb = ohh * 144 + u;
                const float4 A0 = *reinterpret_cast<const float4*>(pb + (rb      ) * 20 + ol * 4);
                const float4 A1 = *reinterpret_cast<const float4*>(pb + (rb +  72) * 20 + ol * 4);
                const float4 C0 = *reinterpret_cast<const float4*>(pb + (rb +  36) * 20 + ol * 4);
                const float4 C1 = *reinterpret_cast<const float4*>(pb + (rb + 108) * 20 + ol * 4);
                p0 += w0.x * A0.x + w0.y * A0.y + w0.z * A0.z + w0.w * A0.w
                    + w1.x * A1.x + w1.y * A1.y + w1.z * A1.z + w1.w * A1.w;
                p1 += w0.x * C0.x + w0.y * C0.y + w0.z * C0.z + w0.w * C0.w
                    + w1.x * C1.x + w1.y * C1.y + w1.z * C1.z + w1.w * C1.w;
            }
            svp[(o * E_ + e) * 4 + uc] = p0;
            svp[((O_ + o) * E_ + e) * 4 + uc] = p1;
        }
        __syncthreads();

        // ---- phase 4: reduce partials + squash -> vv ----
        if (tid < BT * O_) {
            const int bb = tid / O_, o = tid - bb * O_;
            float sv[E_];
            float nsq = 0.f;
            #pragma unroll
            for (int e = 0; e < E_; ++e) {
                const float* p = svp + ((bb * O_ + o) * E_ + e) * 4;
                float s = (p[0] + p[1]) + (p[2] + p[3]);
                sv[e] = s;
                nsq += s * s;
            }
            const float nrm = sqrtf(nsq);
            const float sc = nrm / (1.f + nsq);
            #pragma unroll
            for (int e = 0; e < E_; ++e) vv[(bb * O_ + o) * E_ + e] = sv[e] * sc;
        }
        __syncthreads();

        if (it == ITERS_) break;

        // ---- phase 5: wv[bb,o,u,fg] (into rows 288.. of partial buffer) ----
        {
            float4* wv4 = reinterpret_cast<float4*>(pb + WVO);
            for (int i = tid; i < O_ * U_ * 2; i += T_) {
                const int fgg = i & 1;
                const int ou = i >> 1;
                const int o = ou / U_, u = ou - o * U_;
                const float4* wp = wp4 + ((o * U_ + u) * E_ * 2 + fgg);
                const float* v0 = vv + o * E_;
                const float* v1 = vv + (O_ + o) * E_;
                float4 A = make_float4(0.f,0.f,0.f,0.f);
                float4 Bv = A;
                #pragma unroll
                for (int e = 0; e < E_; ++e) {
                    const float4 w = wp[e * 2];
                    const float ve0 = v0[e], ve1 = v1[e];
                    A.x += ve0 * w.x; A.y += ve0 * w.y; A.z += ve0 * w.z; A.w += ve0 * w.w;
                    Bv.x += ve1 * w.x; Bv.y += ve1 * w.y; Bv.z += ve1 * w.z; Bv.w += ve1 * w.w;
                }
                wv4[(o * U_ + u) * 2 + fgg] = A;
                wv4[((O_ + o) * U_ + u) * 2 + fgg] = Bv;
            }
        }
        __syncthreads();

        // ---- phase 6: c <- normalize_o( c * exp(x . wv) ) ----
        {
            const float4* wv4 = reinterpret_cast<const float4*>(pb + WVO);
            #pragma unroll
            for (int k = 0; k < 4; ++k) {
                const int i = tid + T_ * k;
                const int bb = i / N_, n = i - bb * N_;
                const int u = n >> 5;
                const float4* xp = xs4 + (bb * N_ + n) * 2;
                const float4 x0 = xp[0], x1 = xp[1];
                const float4* wvb = wv4 + (bb * O_ * U_ + u) * 2;
                float* cp = cc + bb * O_ * NP + n;
                float t[O_];
                float ss = 0.f;
                #pragma unroll
                for (int o = 0; o < O_; ++o) {
                    const float4 w0 = wvb[o * U_ * 2], w1 = wvb[o * U_ * 2 + 1];
                    const float d = x0.x * w0.x + x0.y * w0.y + x0.z * w0.z + x0.w * w0.w
                                  + x1.x * w1.x + x1.y * w1.y + x1.z * w1.z + x1.w * w1.w;
                    const float tv = cp[o * NP] * __expf(d);
                    t[o] = tv;
                    ss += tv;
                }
                const float inv = 1.0f / ss;
                #pragma unroll
                for (int o = 0; o < O_; ++o) cp[o * NP] = t[o] * inv;
            }
        }
        __syncthreads();
    }

    // ---- write out[b][o][e] ----
    if (tid < BT * O_ * E_) {
        const int bb = tid / (O_ * E_);
        out[(size_t)(b0 + bb) * (O_ * E_) + (tid - bb * O_ * E_)] = vv[tid];
    }
}

extern "C" void kernel_launch(void* const* d_in, const int* in_sizes, int n_in,
                              void* d_out, int out_size) {
    (void)in_sizes; (void)n_in; (void)out_size;
    const float* x = (const float*)d_in[0];
    const float* W = (const float*)d_in[1];
    float* out = (float*)d_out;

    const size_t smem = (size_t)SM_FLOATS * sizeof(float);  // 218,768 B
    cudaFuncSetAttribute(caps_route_kernel,
                         cudaFuncAttributeMaxDynamicSharedMemorySize, (int)smem);
    caps_route_kernel<<<B_ / BT, T_, smem>>>(x, W, out);
}